// round 1
// baseline (speedup 1.0000x reference)
#include <cuda_runtime.h>
#include <math.h>

#define FULL 0xffffffffu
#define LOG2E 1.4426950408889634f
#define LN2   0.6931471805599453f

// Precomputed log_softmax(W_m, axis=0) [32,32,32] and a0 [32]
__device__ float g_wls[32 * 32 * 32];
__device__ float g_a0[32];

__device__ __forceinline__ float ex2f(float x) {
    float y; asm("ex2.approx.f32 %0, %1;" : "=f"(y) : "f"(x)); return y;
}
__device__ __forceinline__ float lg2f(float x) {
    float y; asm("lg2.approx.f32 %0, %1;" : "=f"(y) : "f"(x)); return y;
}

// ---------------------------------------------------------------------------
// Prep: 1024 threads; thread t = (m, k') computes log_softmax over k of
// W[m, k, k'] (axis=0 of each [K,K] matrix). Threads 0..31 also compute a0.
// ---------------------------------------------------------------------------
__global__ void tt_prep_kernel(const float* __restrict__ W,
                               const float* __restrict__ wk0) {
    int t = threadIdx.x;
    int m = t >> 5, kp = t & 31;

    float v[32];
    float mx = -INFINITY;
#pragma unroll
    for (int k = 0; k < 32; k++) {
        v[k] = W[m * 1024 + k * 32 + kp];
        mx = fmaxf(mx, v[k]);
    }
    float s = 0.f;
#pragma unroll
    for (int k = 0; k < 32; k++) s += expf(v[k] - mx);
    float lse = mx + logf(s);
#pragma unroll
    for (int k = 0; k < 32; k++) g_wls[m * 1024 + k * 32 + kp] = v[k] - lse;

    if (t < 32) {
        float m2 = -INFINITY;
#pragma unroll
        for (int k = 0; k < 32; k++) m2 = fmaxf(m2, wk0[k]);
        float s2 = 0.f;
#pragma unroll
        for (int k = 0; k < 32; k++) s2 += expf(wk0[k] - m2);
        g_a0[t] = wk0[t] - (m2 + logf(s2));
    }
}

// ---------------------------------------------------------------------------
// Main: 512 threads (16 warps) per CTA, each warp handles 2 samples (A, B).
// Lane = output column k'. Wls (128 KB) staged in dynamic smem.
// Per m-step: two-pass exact logsumexp with s[k] held in registers.
// ---------------------------------------------------------------------------
__global__ void __launch_bounds__(512, 1)
tt_main_kernel(const float* __restrict__ L, float* __restrict__ out) {
    extern __shared__ float wls[];  // 32768 floats = 128 KB
    for (int i = threadIdx.x; i < 32768; i += 512) wls[i] = g_wls[i];
    __syncthreads();

    const int warp = threadIdx.x >> 5;
    const int lane = threadIdx.x & 31;
    const int n0 = (blockIdx.x * 16 + warp) * 2;

    const float* LA = L + (size_t)n0 * 32768 + lane;
    const float* LB = LA + 32768;

    float aA = g_a0[lane];
    float aB = aA;

#pragma unroll 1
    for (int m = 0; m < 32; m++) {
        const float* wp = wls + m * 1024 + lane;
        const float* lA = LA + m * 1024;
        const float* lB = LB + m * 1024;

        float sA[32], sB[32];
        float mxA = -INFINITY, mxB = -INFINITY;
#pragma unroll
        for (int k = 0; k < 32; k++) {
            float w   = wp[k * 32];
            float wlA = w + lA[k * 32];
            float wlB = w + lB[k * 32];
            float akA = __shfl_sync(FULL, aA, k);
            float akB = __shfl_sync(FULL, aB, k);
            sA[k] = akA + wlA;
            sB[k] = akB + wlB;
            mxA = fmaxf(mxA, sA[k]);
            mxB = fmaxf(mxB, sB[k]);
        }

        float accA = 0.f, accB = 0.f;
        const float cA = -mxA * LOG2E;
        const float cB = -mxB * LOG2E;
#pragma unroll
        for (int k = 0; k < 32; k++) {
            accA += ex2f(fmaf(sA[k], LOG2E, cA));
            accB += ex2f(fmaf(sB[k], LOG2E, cB));
        }
        aA = fmaf(lg2f(accA), LN2, mxA);
        aB = fmaf(lg2f(accB), LN2, mxB);
    }

    // Final logsumexp across the 32 lanes (columns) for each sample.
    float mA = aA, mB = aB;
#pragma unroll
    for (int off = 16; off; off >>= 1) {
        mA = fmaxf(mA, __shfl_xor_sync(FULL, mA, off));
        mB = fmaxf(mB, __shfl_xor_sync(FULL, mB, off));
    }
    float eA = ex2f((aA - mA) * LOG2E);
    float eB = ex2f((aB - mB) * LOG2E);
#pragma unroll
    for (int off = 16; off; off >>= 1) {
        eA += __shfl_xor_sync(FULL, eA, off);
        eB += __shfl_xor_sync(FULL, eB, off);
    }
    if (lane == 0) {
        out[n0]     = fmaf(lg2f(eA), LN2, mA);
        out[n0 + 1] = fmaf(lg2f(eB), LN2, mB);
    }
}

// ---------------------------------------------------------------------------
// Launch contract
// ---------------------------------------------------------------------------
extern "C" void kernel_launch(void* const* d_in, const int* in_sizes, int n_in,
                              void* d_out, int out_size) {
    const float* L   = (const float*)d_in[0];   // [8192, 32, 32, 32]
    const float* wk0 = (const float*)d_in[1];   // [1, 32]
    const float* W   = (const float*)d_in[2];   // [32, 32, 32]
    float* out = (float*)d_out;                 // [8192]

    (void)in_sizes; (void)n_in; (void)out_size;

    cudaFuncSetAttribute(tt_main_kernel,
                         cudaFuncAttributeMaxDynamicSharedMemorySize, 131072);

    tt_prep_kernel<<<1, 1024>>>(W, wk0);
    tt_main_kernel<<<256, 512, 131072>>>(L, out);
}